// round 13
// baseline (speedup 1.0000x reference)
#include <cuda_runtime.h>
#include <cuda_fp16.h>
#include <cstdint>
#include <math.h>

#define NN 100000
#define EE 3200000
#define LL 8

#define EA_SCALE  (0.9f / 65535.0f)
#define EA_ISCALE (65535.0f / 0.9f)
#define EA_FOLD   (0.1f - 8388608.0f * EA_SCALE)

// ---------------- scratch ----------------
__device__ int4   g_rec_s[EE];        // {src, ea_lo, ea_hi, eid} dst-sorted
__device__ int    g_pos[EE];          // e -> position in dst-sorted order
__device__ float  g_flow_s[EE];       // flow per sorted position (L2-resident)
__device__ int    g_cnt[NN];
__device__ int    g_rowptr[NN + 1];
__device__ int    g_cursor[NN];
__device__ uint2  g_presrc_h[NN * 4]; // per-node 16 fp16 (4 halves per q-lane)
__device__ float4 g_predst[NN * 4];
__device__ float4 g_S[NN * 4];
__device__ float  g_P[NN];
__device__ float  g_balance[NN];
__device__ float  g_insum[NN];
__device__ int    g_blocksums[128];
__device__ float  g_imb;
__device__ int    g_done;

// ---------------- f32x2 helpers ----------------
__device__ __forceinline__ unsigned long long pk2(float lo, float hi) {
    unsigned long long r;
    asm("mov.b64 %0, {%1,%2};" : "=l"(r) : "f"(lo), "f"(hi));
    return r;
}
__device__ __forceinline__ void upk2(unsigned long long v, float& lo, float& hi) {
    asm("mov.b64 {%0,%1}, %2;" : "=f"(lo), "=f"(hi) : "l"(v));
}
__device__ __forceinline__ unsigned long long fma2(unsigned long long a, unsigned long long b, unsigned long long c) {
    unsigned long long d;
    asm("fma.rn.f32x2 %0, %1, %2, %3;" : "=l"(d) : "l"(a), "l"(b), "l"(c));
    return d;
}
__device__ __forceinline__ unsigned long long add2(unsigned long long a, unsigned long long b) {
    unsigned long long d;
    asm("add.rn.f32x2 %0, %1, %2;" : "=l"(d) : "l"(a), "l"(b));
    return d;
}
__device__ __forceinline__ float mag_lo(unsigned int w) {
    unsigned int r;
    asm("prmt.b32 %0, %1, %2, %3;" : "=r"(r) : "r"(w), "r"(0x00004B00u), "r"(0x5410u));
    return __uint_as_float(r);
}
__device__ __forceinline__ float mag_hi(unsigned int w) {
    unsigned int r;
    asm("prmt.b32 %0, %1, %2, %3;" : "=r"(r) : "r"(w), "r"(0x00004B00u), "r"(0x5432u));
    return __uint_as_float(r);
}
__device__ __forceinline__ unsigned long long h2_to_f32x2(unsigned int h2bits) {
    __half2 h = *(__half2*)&h2bits;
    float2 f = __half22float2(h);
    return pk2(f.x, f.y);
}

// ---------------- prep ----------------
__device__ __forceinline__ unsigned int quant_ea(float v) {
    float q = (v - 0.1f) * EA_ISCALE;
    q = fminf(fmaxf(q, 0.f), 65535.f);
    return __float2uint_rn(q);
}

__device__ __forceinline__ bool detect64(const long long* p64) {
    bool is64 = true;
    #pragma unroll
    for (int j = 0; j < 8; j++) {
        long long v = p64[j];
        if (v < 0 || v >= NN) is64 = false;
    }
    return is64;
}

__global__ void count_kernel(const void* ei) {
    int e = blockIdx.x * blockDim.x + threadIdx.x;
    if (e >= EE) return;
    const long long* p64 = (const long long*)ei;
    int d;
    if (detect64(p64)) d = (int)p64[e + EE];
    else               d = ((const int*)ei)[e + EE];
    atomicAdd(&g_cnt[d], 1);
}

__global__ void scan1_kernel() {
    __shared__ int s[1024];
    int tx = threadIdx.x;
    int i = blockIdx.x * 1024 + tx;
    s[tx] = (i < NN) ? g_cnt[i] : 0;
    __syncthreads();
    for (int off = 1; off < 1024; off <<= 1) {
        int t = (tx >= off) ? s[tx - off] : 0;
        __syncthreads();
        s[tx] += t;
        __syncthreads();
    }
    if (i < NN) g_rowptr[i + 1] = s[tx];
    if (tx == 1023) g_blocksums[blockIdx.x] = s[1023];
}

__global__ void scan23_kernel(int nblocks) {
    __shared__ int sb[128];
    int t = threadIdx.x;
    if (t < 128) sb[t] = (t < nblocks) ? g_blocksums[t] : 0;
    __syncthreads();
    if (t == 0) {
        int run = 0;
        for (int b = 0; b < nblocks; b++) { int c = sb[b]; sb[b] = run; run += c; }
    }
    __syncthreads();
    int i = blockIdx.x * blockDim.x + t;
    if (i >= NN) return;
    int off = sb[i >> 10];
    int rp = g_rowptr[i + 1] + off;
    g_rowptr[i + 1] = rp;
    g_cursor[i] = rp - g_cnt[i];
    g_cnt[i] = 0;
    g_balance[i] = 0.f;
    if (i == 0) { g_rowptr[0] = 0; g_imb = 0.f; g_done = 0; }
}

__global__ void scatter_kernel(const void* ei, const float4* __restrict__ ea4) {
    int e = blockIdx.x * blockDim.x + threadIdx.x;
    if (e >= EE) return;
    const long long* p64 = (const long long*)ei;
    int s, d;
    if (detect64(p64)) {
        s = (int)p64[e]; d = (int)p64[e + EE];
    } else {
        const int* p32 = (const int*)ei;
        s = p32[e]; d = p32[e + EE];
    }
    float4 ea = ea4[e];
    int p = atomicAdd(&g_cursor[d], 1);
    int4 rec;
    rec.x = s;
    rec.y = (int)(quant_ea(ea.x) | (quant_ea(ea.y) << 16));
    rec.z = (int)(quant_ea(ea.z) | (quant_ea(ea.w) << 16));
    rec.w = e;
    g_rec_s[p] = rec;
    g_pos[e] = p;       // coalesced permutation record for the flow remap
}

// ---------------- per-layer node kernel (shuffle-reduced X computation) ----------------
__global__ void node_kernel(const float4* __restrict__ x4,
                            const float* __restrict__ W1, const float* __restrict__ b1,
                            const float* __restrict__ W2, const float* __restrict__ b2,
                            int l) {
    __shared__ float sW1[384], sb1[16], sW2[96], sb2[6];
    int t = threadIdx.x;
    for (int i = t; i < 384; i += blockDim.x) sW1[i] = W1[l * 384 + i];
    if (t < 16) sb1[t] = b1[l * 16 + t];
    if (l > 0) {
        for (int i = t; i < 96; i += blockDim.x) sW2[i] = W2[(l - 1) * 96 + i];
        if (t < 6) sb2[t] = b2[(l - 1) * 6 + t];
    }
    __syncthreads();
    int tid = blockIdx.x * blockDim.x + t;
    if (tid >= NN * 4) return;
    int n = tid >> 2, q = tid & 3;

    float X[6];
    if (l == 0) {
        #pragma unroll
        for (int k = 0; k < 6; k++) X[k] = 0.f;
    } else {
        int cnt = g_rowptr[n + 1] - g_rowptr[n];
        float inv = 1.0f / (float)max(cnt, 1);
        float fc = (float)cnt;
        float4 sq = g_S[n * 4 + q];        // this lane's quarter only
        float pk_[6];
        #pragma unroll
        for (int k = 0; k < 6; k++) {
            float a = sq.x * sW2[(q * 4 + 0) * 6 + k];
            a = fmaf(sq.y, sW2[(q * 4 + 1) * 6 + k], a);
            a = fmaf(sq.z, sW2[(q * 4 + 2) * 6 + k], a);
            a = fmaf(sq.w, sW2[(q * 4 + 3) * 6 + k], a);
            pk_[k] = a;
        }
        #pragma unroll
        for (int off = 1; off <= 2; off <<= 1) {
            #pragma unroll
            for (int k = 0; k < 6; k++)
                pk_[k] += __shfl_xor_sync(0xffffffffu, pk_[k], off);
        }
        #pragma unroll
        for (int k = 0; k < 6; k++)
            X[k] = fmaxf(fmaf(fc, sb2[k], pk_[k]) * inv, 0.f);
    }
    float4 na = x4[n];
    float ps[4], pd[4];
    #pragma unroll
    for (int jj = 0; jj < 4; jj++) {
        int j = q * 4 + jj;
        float a = 0.f, b = sb1[j];
        #pragma unroll
        for (int i = 0; i < 6; i++) {
            a = fmaf(X[i], sW1[i * 16 + j], a);
            b = fmaf(X[i], sW1[(6 + i) * 16 + j], b);
        }
        a = fmaf(na.x, sW1[12 * 16 + j], a);
        a = fmaf(na.y, sW1[13 * 16 + j], a);
        a = fmaf(na.z, sW1[14 * 16 + j], a);
        a = fmaf(na.w, sW1[15 * 16 + j], a);
        b = fmaf(na.x, sW1[16 * 16 + j], b);
        b = fmaf(na.y, sW1[17 * 16 + j], b);
        b = fmaf(na.z, sW1[18 * 16 + j], b);
        b = fmaf(na.w, sW1[19 * 16 + j], b);
        ps[jj] = a; pd[jj] = b;
    }
    __half2 h01 = __floats2half2_rn(ps[0], ps[1]);
    __half2 h23 = __floats2half2_rn(ps[2], ps[3]);
    uint2 u;
    u.x = *(unsigned int*)&h01;
    u.y = *(unsigned int*)&h23;
    g_presrc_h[n * 4 + q] = u;
    g_predst[n * 4 + q] = make_float4(pd[0], pd[1], pd[2], pd[3]);
}

// ---------------- per-layer edge kernel: QUARTER-WARP per node (round-8 exact) ----------------
__global__ void __launch_bounds__(128) edge_kernel(const float* __restrict__ W1, int l) {
    int lane = threadIdx.x & 31;
    int grp = lane >> 3;
    int q = lane & 3;
    int eslot = (lane >> 2) & 1;
    const float* wp = W1 + l * 384 + 20 * 16 + q * 4;
    float4 w0 = *(const float4*)(wp);
    float4 w1 = *(const float4*)(wp + 16);
    float4 w2 = *(const float4*)(wp + 32);
    float4 w3 = *(const float4*)(wp + 48);
    float4 base;
    base.x = EA_FOLD * (w0.x + w1.x + w2.x + w3.x);
    base.y = EA_FOLD * (w0.y + w1.y + w2.y + w3.y);
    base.z = EA_FOLD * (w0.z + w1.z + w2.z + w3.z);
    base.w = EA_FOLD * (w0.w + w1.w + w2.w + w3.w);
    unsigned long long W0a = pk2(w0.x * EA_SCALE, w0.y * EA_SCALE);
    unsigned long long W0b = pk2(w0.z * EA_SCALE, w0.w * EA_SCALE);
    unsigned long long W1a = pk2(w1.x * EA_SCALE, w1.y * EA_SCALE);
    unsigned long long W1b = pk2(w1.z * EA_SCALE, w1.w * EA_SCALE);
    unsigned long long W2a = pk2(w2.x * EA_SCALE, w2.y * EA_SCALE);
    unsigned long long W2b = pk2(w2.z * EA_SCALE, w2.w * EA_SCALE);
    unsigned long long W3a = pk2(w3.x * EA_SCALE, w3.y * EA_SCALE);
    unsigned long long W3b = pk2(w3.z * EA_SCALE, w3.w * EA_SCALE);

    int warp = (blockIdx.x * blockDim.x + threadIdx.x) >> 5;
    int nwarps = (gridDim.x * blockDim.x) >> 5;
    const int NQUAD = NN / 4;
    for (int idx = warp; idx < NQUAD; idx += nwarps) {
        int n = idx * 4 + grp;
        int rs = g_rowptr[n], re = g_rowptr[n + 1];
        float4 pd = g_predst[n * 4 + q];
        unsigned long long pdA = pk2(pd.x + base.x, pd.y + base.y);
        unsigned long long pdB = pk2(pd.z + base.z, pd.w + base.w);
        float ax = 0.f, ay = 0.f, az = 0.f, aw = 0.f;
        int last = re - 1;
        for (int p0 = rs; p0 < re; p0 += 4) {
            int pA = p0 + eslot;
            int pB = pA + 2;
            bool vA = pA < re;
            bool vB = pB < re;
            int4 cA = g_rec_s[min(pA, last)];
            int4 cB = g_rec_s[min(pB, last)];
            uint2 hA = g_presrc_h[cA.x * 4 + q];
            uint2 hB = g_presrc_h[cB.x * 4 + q];
            {
                unsigned long long ps01 = h2_to_f32x2(hA.x);
                unsigned long long ps23 = h2_to_f32x2(hA.y);
                unsigned int ex = (unsigned int)cA.y, ey = (unsigned int)cA.z;
                float f0 = mag_lo(ex), f1 = mag_hi(ex);
                float f2 = mag_lo(ey), f3 = mag_hi(ey);
                unsigned long long A0 = pk2(f0, f0), A1 = pk2(f1, f1);
                unsigned long long A2 = pk2(f2, f2), A3 = pk2(f3, f3);
                unsigned long long h01 = add2(ps01, pdA);
                unsigned long long h23 = add2(ps23, pdB);
                h01 = fma2(A0, W0a, h01); h23 = fma2(A0, W0b, h23);
                h01 = fma2(A1, W1a, h01); h23 = fma2(A1, W1b, h23);
                h01 = fma2(A2, W2a, h01); h23 = fma2(A2, W2b, h23);
                h01 = fma2(A3, W3a, h01); h23 = fma2(A3, W3b, h23);
                float hx, hy, hz, hw;
                upk2(h01, hx, hy); upk2(h23, hz, hw);
                if (vA) {
                    ax += fmaxf(hx, 0.f); ay += fmaxf(hy, 0.f);
                    az += fmaxf(hz, 0.f); aw += fmaxf(hw, 0.f);
                }
            }
            {
                unsigned long long ps01 = h2_to_f32x2(hB.x);
                unsigned long long ps23 = h2_to_f32x2(hB.y);
                unsigned int ex = (unsigned int)cB.y, ey = (unsigned int)cB.z;
                float f0 = mag_lo(ex), f1 = mag_hi(ex);
                float f2 = mag_lo(ey), f3 = mag_hi(ey);
                unsigned long long A0 = pk2(f0, f0), A1 = pk2(f1, f1);
                unsigned long long A2 = pk2(f2, f2), A3 = pk2(f3, f3);
                unsigned long long h01 = add2(ps01, pdA);
                unsigned long long h23 = add2(ps23, pdB);
                h01 = fma2(A0, W0a, h01); h23 = fma2(A0, W0b, h23);
                h01 = fma2(A1, W1a, h01); h23 = fma2(A1, W1b, h23);
                h01 = fma2(A2, W2a, h01); h23 = fma2(A2, W2b, h23);
                h01 = fma2(A3, W3a, h01); h23 = fma2(A3, W3b, h23);
                float hx, hy, hz, hw;
                upk2(h01, hx, hy); upk2(h23, hz, hw);
                if (vB) {
                    ax += fmaxf(hx, 0.f); ay += fmaxf(hy, 0.f);
                    az += fmaxf(hz, 0.f); aw += fmaxf(hw, 0.f);
                }
            }
        }
        ax += __shfl_xor_sync(0xffffffffu, ax, 4);
        ay += __shfl_xor_sync(0xffffffffu, ay, 4);
        az += __shfl_xor_sync(0xffffffffu, az, 4);
        aw += __shfl_xor_sync(0xffffffffu, aw, 4);
        if (eslot == 0) g_S[n * 4 + q] = make_float4(ax, ay, az, aw);
    }
}

// ---------------- epilogue ----------------
__global__ void final_kernel(const float* __restrict__ x,
                             const float* __restrict__ W2, const float* __restrict__ b2,
                             const float* __restrict__ Wf, const float* __restrict__ bf,
                             float* __restrict__ out) {
    __shared__ float sW2[96], sb2[6], sWf[6], sbf;
    int t = threadIdx.x;
    for (int i = t; i < 96; i += blockDim.x) sW2[i] = W2[7 * 96 + i];
    if (t < 6) { sb2[t] = b2[7 * 6 + t]; sWf[t] = Wf[t]; }
    if (t == 0) sbf = bf[0];
    __syncthreads();
    int n = blockIdx.x * blockDim.x + t;
    if (n >= NN) return;
    int cnt = g_rowptr[n + 1] - g_rowptr[n];
    float inv = 1.0f / (float)max(cnt, 1);
    float fc = (float)cnt;
    float4 s0 = g_S[n * 4 + 0], s1 = g_S[n * 4 + 1], s2 = g_S[n * 4 + 2], s3 = g_S[n * 4 + 3];
    float Sv[16] = { s0.x, s0.y, s0.z, s0.w, s1.x, s1.y, s1.z, s1.w,
                     s2.x, s2.y, s2.z, s2.w, s3.x, s3.y, s3.z, s3.w };
    float P = sbf;
    #pragma unroll
    for (int k = 0; k < 6; k++) {
        float a = fc * sb2[k];
        #pragma unroll
        for (int j = 0; j < 16; j++) a = fmaf(Sv[j], sW2[j * 6 + k], a);
        float Xk = fmaxf(a * inv, 0.f);
        P = fmaf(Xk, sWf[k], P);
    }
    P = fmaxf(P, 0.f);
    out[n] = P;
    float fixedv = x[n * 4 + 3];
    g_P[n] = (fixedv != 0.f) ? fixedv : P;
}

// flows: CSR per node; flow stored COALESCED at its sorted position (L2-resident).
__global__ void __launch_bounds__(128) flows_kernel() {
    int lane = threadIdx.x & 31;
    int warp = (blockIdx.x * blockDim.x + threadIdx.x) >> 5;
    int nwarps = (gridDim.x * blockDim.x) >> 5;
    for (int n = warp; n < NN; n += nwarps) {
        int rs = g_rowptr[n], re = g_rowptr[n + 1];
        float Pd = g_P[n];
        float Pd2 = Pd * Pd;
        float acc = 0.f;
        for (int p = rs + lane; p < re; p += 32) {
            int4 rec = g_rec_s[p];
            float Ps = g_P[rec.x];
            float dp2 = Ps * Ps - Pd2;
            float k = 0.1f + (float)((unsigned int)rec.y & 0xFFFFu) * EA_SCALE;
            float v = sqrtf(fabsf(dp2) / k + 1e-6f);
            float f = (dp2 > 0.f) ? v : ((dp2 < 0.f) ? -v : 0.f);
            g_flow_s[p] = f;                       // coalesced (was random out write)
            acc += f;
            atomicAdd(&g_balance[rec.x], -f);
        }
        #pragma unroll
        for (int off = 16; off > 0; off >>= 1) acc += __shfl_xor_sync(0xffffffffu, acc, off);
        if (lane == 0) g_insum[n] = acc;
    }
}

// remap: original-order output. pos read + out write coalesced; flow read hits L2.
__global__ void remap_kernel(float* __restrict__ out) {
    int e = blockIdx.x * blockDim.x + threadIdx.x;
    if (e >= EE) return;
    out[NN + e] = g_flow_s[g_pos[e]];
}

__global__ void reduce_kernel(const float* __restrict__ x, float* __restrict__ out) {
    __shared__ float sred[8];
    float loc = 0.f;
    for (int n = blockIdx.x * blockDim.x + threadIdx.x; n < NN; n += gridDim.x * blockDim.x) {
        float v = g_insum[n] + g_balance[n] + x[n * 4];
        loc += v * v;
    }
    #pragma unroll
    for (int off = 16; off > 0; off >>= 1) loc += __shfl_xor_sync(0xffffffffu, loc, off);
    int wid = threadIdx.x >> 5;
    if ((threadIdx.x & 31) == 0) sred[wid] = loc;
    __syncthreads();
    if (threadIdx.x == 0) {
        float tot = 0.f;
        for (int w = 0; w < (int)(blockDim.x >> 5); w++) tot += sred[w];
        atomicAdd(&g_imb, tot);
        __threadfence();
        int d = atomicAdd(&g_done, 1);
        if (d == (int)gridDim.x - 1) out[NN + EE] = sqrtf(g_imb);
    }
}

// ---------------- launch ----------------
extern "C" void kernel_launch(void* const* d_in, const int* in_sizes, int n_in,
                              void* d_out, int out_size) {
    const float*  x    = (const float*)d_in[0];
    const float4* x4   = (const float4*)d_in[0];
    const float4* ea4  = (const float4*)d_in[1];
    const void*   ei   = d_in[2];
    const float*  W1   = (const float*)d_in[3];
    const float*  b1   = (const float*)d_in[4];
    const float*  W2   = (const float*)d_in[5];
    const float*  b2   = (const float*)d_in[6];
    const float*  Wf   = (const float*)d_in[7];
    const float*  bf   = (const float*)d_in[8];
    float* out = (float*)d_out;

    const int TB = 256;
    const int gN  = (NN + TB - 1) / TB;
    const int gN4 = (NN * 4 + TB - 1) / TB;
    const int gE  = (EE + TB - 1) / TB;
    const int nScanBlocks = (NN + 1023) / 1024;

    count_kernel<<<gE, TB>>>(ei);
    scan1_kernel<<<nScanBlocks, 1024>>>();
    scan23_kernel<<<gN, TB>>>(nScanBlocks);
    scatter_kernel<<<gE, TB>>>(ei, ea4);

    for (int l = 0; l < LL; l++) {
        node_kernel<<<gN4, TB>>>(x4, W1, b1, W2, b2, l);
        edge_kernel<<<6250, 128>>>(W1, l);
    }

    final_kernel<<<gN, TB>>>(x, W2, b2, Wf, bf, out);
    flows_kernel<<<4096, 128>>>();
    remap_kernel<<<gE, TB>>>(out);
    reduce_kernel<<<512, TB>>>(x, out);
}

// round 15
// speedup vs baseline: 1.0331x; 1.0331x over previous
#include <cuda_runtime.h>
#include <cuda_fp16.h>
#include <cstdint>
#include <math.h>

#define NN 100000
#define EE 3200000
#define LL 8

#define EA_SCALE  (0.9f / 65535.0f)
#define EA_ISCALE (65535.0f / 0.9f)
#define EA_FOLD   (0.1f - 8388608.0f * EA_SCALE)

// ---------------- scratch ----------------
__device__ int4   g_rec_s[EE];        // {src, ea_lo, ea_hi, eid} dst-sorted
__device__ int    g_cnt[NN];
__device__ int    g_rowptr[NN + 1];
__device__ int    g_cursor[NN];
__device__ uint2  g_presrc_h[NN * 4]; // per-node 16 fp16 (4 halves per q-lane)
__device__ float4 g_predst[NN * 4];
__device__ float4 g_S[NN * 4];
__device__ float  g_P[NN];
__device__ float  g_balance[NN];
__device__ float  g_insum[NN];
__device__ int    g_blocksums[128];
__device__ float  g_imb;
__device__ int    g_done;

// ---------------- f32x2 helpers ----------------
__device__ __forceinline__ unsigned long long pk2(float lo, float hi) {
    unsigned long long r;
    asm("mov.b64 %0, {%1,%2};" : "=l"(r) : "f"(lo), "f"(hi));
    return r;
}
__device__ __forceinline__ void upk2(unsigned long long v, float& lo, float& hi) {
    asm("mov.b64 {%0,%1}, %2;" : "=f"(lo), "=f"(hi) : "l"(v));
}
__device__ __forceinline__ unsigned long long fma2(unsigned long long a, unsigned long long b, unsigned long long c) {
    unsigned long long d;
    asm("fma.rn.f32x2 %0, %1, %2, %3;" : "=l"(d) : "l"(a), "l"(b), "l"(c));
    return d;
}
__device__ __forceinline__ unsigned long long add2(unsigned long long a, unsigned long long b) {
    unsigned long long d;
    asm("add.rn.f32x2 %0, %1, %2;" : "=l"(d) : "l"(a), "l"(b));
    return d;
}
__device__ __forceinline__ float mag_lo(unsigned int w) {
    unsigned int r;
    asm("prmt.b32 %0, %1, %2, %3;" : "=r"(r) : "r"(w), "r"(0x00004B00u), "r"(0x5410u));
    return __uint_as_float(r);
}
__device__ __forceinline__ float mag_hi(unsigned int w) {
    unsigned int r;
    asm("prmt.b32 %0, %1, %2, %3;" : "=r"(r) : "r"(w), "r"(0x00004B00u), "r"(0x5432u));
    return __uint_as_float(r);
}
__device__ __forceinline__ unsigned long long h2_to_f32x2(unsigned int h2bits) {
    __half2 h = *(__half2*)&h2bits;
    float2 f = __half22float2(h);
    return pk2(f.x, f.y);
}

// ---------------- prep ----------------
__device__ __forceinline__ unsigned int quant_ea(float v) {
    float q = (v - 0.1f) * EA_ISCALE;
    q = fminf(fmaxf(q, 0.f), 65535.f);
    return __float2uint_rn(q);
}

__device__ __forceinline__ bool detect64(const long long* p64) {
    bool is64 = true;
    #pragma unroll
    for (int j = 0; j < 8; j++) {
        long long v = p64[j];
        if (v < 0 || v >= NN) is64 = false;
    }
    return is64;
}

__global__ void count_kernel(const void* ei) {
    int e = blockIdx.x * blockDim.x + threadIdx.x;
    if (e >= EE) return;
    const long long* p64 = (const long long*)ei;
    int d;
    if (detect64(p64)) d = (int)p64[e + EE];
    else               d = ((const int*)ei)[e + EE];
    atomicAdd(&g_cnt[d], 1);
}

__global__ void scan1_kernel() {
    __shared__ int s[1024];
    int tx = threadIdx.x;
    int i = blockIdx.x * 1024 + tx;
    s[tx] = (i < NN) ? g_cnt[i] : 0;
    __syncthreads();
    for (int off = 1; off < 1024; off <<= 1) {
        int t = (tx >= off) ? s[tx - off] : 0;
        __syncthreads();
        s[tx] += t;
        __syncthreads();
    }
    if (i < NN) g_rowptr[i + 1] = s[tx];
    if (tx == 1023) g_blocksums[blockIdx.x] = s[1023];
}

__global__ void scan23_kernel(int nblocks) {
    __shared__ int sb[128];
    int t = threadIdx.x;
    if (t < 128) sb[t] = (t < nblocks) ? g_blocksums[t] : 0;
    __syncthreads();
    if (t == 0) {
        int run = 0;
        for (int b = 0; b < nblocks; b++) { int c = sb[b]; sb[b] = run; run += c; }
    }
    __syncthreads();
    int i = blockIdx.x * blockDim.x + t;
    if (i >= NN) return;
    int off = sb[i >> 10];
    int rp = g_rowptr[i + 1] + off;
    g_rowptr[i + 1] = rp;
    g_cursor[i] = rp - g_cnt[i];
    g_cnt[i] = 0;
    g_balance[i] = 0.f;
    if (i == 0) { g_rowptr[0] = 0; g_imb = 0.f; g_done = 0; }
}

__global__ void scatter_kernel(const void* ei, const float4* __restrict__ ea4) {
    int e = blockIdx.x * blockDim.x + threadIdx.x;
    if (e >= EE) return;
    const long long* p64 = (const long long*)ei;
    int s, d;
    if (detect64(p64)) {
        s = (int)p64[e]; d = (int)p64[e + EE];
    } else {
        const int* p32 = (const int*)ei;
        s = p32[e]; d = p32[e + EE];
    }
    float4 ea = ea4[e];
    int p = atomicAdd(&g_cursor[d], 1);
    int4 rec;
    rec.x = s;
    rec.y = (int)(quant_ea(ea.x) | (quant_ea(ea.y) << 16));
    rec.z = (int)(quant_ea(ea.z) | (quant_ea(ea.w) << 16));
    rec.w = e;
    g_rec_s[p] = rec;
}

// ---------------- per-layer node kernel (shuffle-reduced X computation) ----------------
__global__ void node_kernel(const float4* __restrict__ x4,
                            const float* __restrict__ W1, const float* __restrict__ b1,
                            const float* __restrict__ W2, const float* __restrict__ b2,
                            int l) {
    __shared__ float sW1[384], sb1[16], sW2[96], sb2[6];
    int t = threadIdx.x;
    for (int i = t; i < 384; i += blockDim.x) sW1[i] = W1[l * 384 + i];
    if (t < 16) sb1[t] = b1[l * 16 + t];
    if (l > 0) {
        for (int i = t; i < 96; i += blockDim.x) sW2[i] = W2[(l - 1) * 96 + i];
        if (t < 6) sb2[t] = b2[(l - 1) * 6 + t];
    }
    __syncthreads();
    int tid = blockIdx.x * blockDim.x + t;
    if (tid >= NN * 4) return;
    int n = tid >> 2, q = tid & 3;

    float X[6];
    if (l == 0) {
        #pragma unroll
        for (int k = 0; k < 6; k++) X[k] = 0.f;
    } else {
        int cnt = g_rowptr[n + 1] - g_rowptr[n];
        float inv = 1.0f / (float)max(cnt, 1);
        float fc = (float)cnt;
        float4 sq = g_S[n * 4 + q];        // this lane's quarter only
        float pk_[6];
        #pragma unroll
        for (int k = 0; k < 6; k++) {
            float a = sq.x * sW2[(q * 4 + 0) * 6 + k];
            a = fmaf(sq.y, sW2[(q * 4 + 1) * 6 + k], a);
            a = fmaf(sq.z, sW2[(q * 4 + 2) * 6 + k], a);
            a = fmaf(sq.w, sW2[(q * 4 + 3) * 6 + k], a);
            pk_[k] = a;
        }
        #pragma unroll
        for (int off = 1; off <= 2; off <<= 1) {
            #pragma unroll
            for (int k = 0; k < 6; k++)
                pk_[k] += __shfl_xor_sync(0xffffffffu, pk_[k], off);
        }
        #pragma unroll
        for (int k = 0; k < 6; k++)
            X[k] = fmaxf(fmaf(fc, sb2[k], pk_[k]) * inv, 0.f);
    }
    float4 na = x4[n];
    float ps[4], pd[4];
    #pragma unroll
    for (int jj = 0; jj < 4; jj++) {
        int j = q * 4 + jj;
        float a = 0.f, b = sb1[j];
        #pragma unroll
        for (int i = 0; i < 6; i++) {
            a = fmaf(X[i], sW1[i * 16 + j], a);
            b = fmaf(X[i], sW1[(6 + i) * 16 + j], b);
        }
        a = fmaf(na.x, sW1[12 * 16 + j], a);
        a = fmaf(na.y, sW1[13 * 16 + j], a);
        a = fmaf(na.z, sW1[14 * 16 + j], a);
        a = fmaf(na.w, sW1[15 * 16 + j], a);
        b = fmaf(na.x, sW1[16 * 16 + j], b);
        b = fmaf(na.y, sW1[17 * 16 + j], b);
        b = fmaf(na.z, sW1[18 * 16 + j], b);
        b = fmaf(na.w, sW1[19 * 16 + j], b);
        ps[jj] = a; pd[jj] = b;
    }
    __half2 h01 = __floats2half2_rn(ps[0], ps[1]);
    __half2 h23 = __floats2half2_rn(ps[2], ps[3]);
    uint2 u;
    u.x = *(unsigned int*)&h01;
    u.y = *(unsigned int*)&h23;
    g_presrc_h[n * 4 + q] = u;
    g_predst[n * 4 + q] = make_float4(pd[0], pd[1], pd[2], pd[3]);
}

// ---------------- per-layer edge kernel: QUARTER-WARP per node, 3-stage pipeline ----------------
// 8 lanes per node (grp = lane>>3, 0..3): eslot = (lane>>2)&1, q = lane&3.
// Trip i computes with data loaded 1 (gather) / 2 (record) iterations earlier.
__global__ void __launch_bounds__(128) edge_kernel(const float* __restrict__ W1, int l) {
    int lane = threadIdx.x & 31;
    int grp = lane >> 3;
    int q = lane & 3;
    int eslot = (lane >> 2) & 1;
    const float* wp = W1 + l * 384 + 20 * 16 + q * 4;
    float4 w0 = *(const float4*)(wp);
    float4 w1 = *(const float4*)(wp + 16);
    float4 w2 = *(const float4*)(wp + 32);
    float4 w3 = *(const float4*)(wp + 48);
    float4 base;
    base.x = EA_FOLD * (w0.x + w1.x + w2.x + w3.x);
    base.y = EA_FOLD * (w0.y + w1.y + w2.y + w3.y);
    base.z = EA_FOLD * (w0.z + w1.z + w2.z + w3.z);
    base.w = EA_FOLD * (w0.w + w1.w + w2.w + w3.w);
    unsigned long long W0a = pk2(w0.x * EA_SCALE, w0.y * EA_SCALE);
    unsigned long long W0b = pk2(w0.z * EA_SCALE, w0.w * EA_SCALE);
    unsigned long long W1a = pk2(w1.x * EA_SCALE, w1.y * EA_SCALE);
    unsigned long long W1b = pk2(w1.z * EA_SCALE, w1.w * EA_SCALE);
    unsigned long long W2a = pk2(w2.x * EA_SCALE, w2.y * EA_SCALE);
    unsigned long long W2b = pk2(w2.z * EA_SCALE, w2.w * EA_SCALE);
    unsigned long long W3a = pk2(w3.x * EA_SCALE, w3.y * EA_SCALE);
    unsigned long long W3b = pk2(w3.z * EA_SCALE, w3.w * EA_SCALE);

    int warp = (blockIdx.x * blockDim.x + threadIdx.x) >> 5;
    int nwarps = (gridDim.x * blockDim.x) >> 5;
    const int NQUAD = NN / 4;
    for (int idx = warp; idx < NQUAD; idx += nwarps) {
        int n = idx * 4 + grp;
        int rs = g_rowptr[n], re = g_rowptr[n + 1];
        float4 pd = g_predst[n * 4 + q];
        unsigned long long pdA = pk2(pd.x + base.x, pd.y + base.y);
        unsigned long long pdB = pk2(pd.z + base.z, pd.w + base.w);
        float ax = 0.f, ay = 0.f, az = 0.f, aw = 0.f;
        if (re > rs) {
            int last = re - 1;
            int p0base = rs + eslot;
            // pipeline prologue: rec for trips 0 and 1, gather for trip 0
            int4 cA0 = g_rec_s[min(p0base,     last)];
            int4 cB0 = g_rec_s[min(p0base + 2, last)];
            int4 cA1 = g_rec_s[min(p0base + 4, last)];
            int4 cB1 = g_rec_s[min(p0base + 6, last)];
            uint2 hA0 = g_presrc_h[cA0.x * 4 + q];
            uint2 hB0 = g_presrc_h[cB0.x * 4 + q];
            for (int p0 = rs; p0 < re; p0 += 4) {
                // prefetch rec for trip+2
                int nA = p0 + 8 + eslot;
                int4 cA2 = g_rec_s[min(nA,     last)];
                int4 cB2 = g_rec_s[min(nA + 2, last)];
                // prefetch gather for trip+1 (its rec arrived last iteration)
                uint2 hA1 = g_presrc_h[cA1.x * 4 + q];
                uint2 hB1 = g_presrc_h[cB1.x * 4 + q];
                bool vA = (p0 + eslot) < re;
                bool vB = (p0 + 2 + eslot) < re;
                {
                    unsigned long long ps01 = h2_to_f32x2(hA0.x);
                    unsigned long long ps23 = h2_to_f32x2(hA0.y);
                    unsigned int ex = (unsigned int)cA0.y, ey = (unsigned int)cA0.z;
                    float f0 = mag_lo(ex), f1 = mag_hi(ex);
                    float f2 = mag_lo(ey), f3 = mag_hi(ey);
                    unsigned long long A0 = pk2(f0, f0), A1 = pk2(f1, f1);
                    unsigned long long A2 = pk2(f2, f2), A3 = pk2(f3, f3);
                    unsigned long long h01 = add2(ps01, pdA);
                    unsigned long long h23 = add2(ps23, pdB);
                    h01 = fma2(A0, W0a, h01); h23 = fma2(A0, W0b, h23);
                    h01 = fma2(A1, W1a, h01); h23 = fma2(A1, W1b, h23);
                    h01 = fma2(A2, W2a, h01); h23 = fma2(A2, W2b, h23);
                    h01 = fma2(A3, W3a, h01); h23 = fma2(A3, W3b, h23);
                    float hx, hy, hz, hw;
                    upk2(h01, hx, hy); upk2(h23, hz, hw);
                    if (vA) {
                        ax += fmaxf(hx, 0.f); ay += fmaxf(hy, 0.f);
                        az += fmaxf(hz, 0.f); aw += fmaxf(hw, 0.f);
                    }
                }
                {
                    unsigned long long ps01 = h2_to_f32x2(hB0.x);
                    unsigned long long ps23 = h2_to_f32x2(hB0.y);
                    unsigned int ex = (unsigned int)cB0.y, ey = (unsigned int)cB0.z;
                    float f0 = mag_lo(ex), f1 = mag_hi(ex);
                    float f2 = mag_lo(ey), f3 = mag_hi(ey);
                    unsigned long long A0 = pk2(f0, f0), A1 = pk2(f1, f1);
                    unsigned long long A2 = pk2(f2, f2), A3 = pk2(f3, f3);
                    unsigned long long h01 = add2(ps01, pdA);
                    unsigned long long h23 = add2(ps23, pdB);
                    h01 = fma2(A0, W0a, h01); h23 = fma2(A0, W0b, h23);
                    h01 = fma2(A1, W1a, h01); h23 = fma2(A1, W1b, h23);
                    h01 = fma2(A2, W2a, h01); h23 = fma2(A2, W2b, h23);
                    h01 = fma2(A3, W3a, h01); h23 = fma2(A3, W3b, h23);
                    float hx, hy, hz, hw;
                    upk2(h01, hx, hy); upk2(h23, hz, hw);
                    if (vB) {
                        ax += fmaxf(hx, 0.f); ay += fmaxf(hy, 0.f);
                        az += fmaxf(hz, 0.f); aw += fmaxf(hw, 0.f);
                    }
                }
                // rotate pipeline
                cA0 = cA1; cB0 = cB1;
                cA1 = cA2; cB1 = cB2;
                hA0 = hA1; hB0 = hB1;
            }
        }
        ax += __shfl_xor_sync(0xffffffffu, ax, 4);
        ay += __shfl_xor_sync(0xffffffffu, ay, 4);
        az += __shfl_xor_sync(0xffffffffu, az, 4);
        aw += __shfl_xor_sync(0xffffffffu, aw, 4);
        if (eslot == 0) g_S[n * 4 + q] = make_float4(ax, ay, az, aw);
    }
}

// ---------------- epilogue ----------------
__global__ void final_kernel(const float* __restrict__ x,
                             const float* __restrict__ W2, const float* __restrict__ b2,
                             const float* __restrict__ Wf, const float* __restrict__ bf,
                             float* __restrict__ out) {
    __shared__ float sW2[96], sb2[6], sWf[6], sbf;
    int t = threadIdx.x;
    for (int i = t; i < 96; i += blockDim.x) sW2[i] = W2[7 * 96 + i];
    if (t < 6) { sb2[t] = b2[7 * 6 + t]; sWf[t] = Wf[t]; }
    if (t == 0) sbf = bf[0];
    __syncthreads();
    int n = blockIdx.x * blockDim.x + t;
    if (n >= NN) return;
    int cnt = g_rowptr[n + 1] - g_rowptr[n];
    float inv = 1.0f / (float)max(cnt, 1);
    float fc = (float)cnt;
    float4 s0 = g_S[n * 4 + 0], s1 = g_S[n * 4 + 1], s2 = g_S[n * 4 + 2], s3 = g_S[n * 4 + 3];
    float Sv[16] = { s0.x, s0.y, s0.z, s0.w, s1.x, s1.y, s1.z, s1.w,
                     s2.x, s2.y, s2.z, s2.w, s3.x, s3.y, s3.z, s3.w };
    float P = sbf;
    #pragma unroll
    for (int k = 0; k < 6; k++) {
        float a = fc * sb2[k];
        #pragma unroll
        for (int j = 0; j < 16; j++) a = fmaf(Sv[j], sW2[j * 6 + k], a);
        float Xk = fmaxf(a * inv, 0.f);
        P = fmaf(Xk, sWf[k], P);
    }
    P = fmaxf(P, 0.f);
    out[n] = P;
    float fixedv = x[n * 4 + 3];
    g_P[n] = (fixedv != 0.f) ? fixedv : P;
}

__global__ void __launch_bounds__(128) flows_kernel(float* __restrict__ out) {
    int lane = threadIdx.x & 31;
    int warp = (blockIdx.x * blockDim.x + threadIdx.x) >> 5;
    int nwarps = (gridDim.x * blockDim.x) >> 5;
    for (int n = warp; n < NN; n += nwarps) {
        int rs = g_rowptr[n], re = g_rowptr[n + 1];
        float Pd = g_P[n];
        float Pd2 = Pd * Pd;
        float acc = 0.f;
        for (int p = rs + lane; p < re; p += 32) {
            int4 rec = g_rec_s[p];
            float Ps = g_P[rec.x];
            float dp2 = Ps * Ps - Pd2;
            float k = 0.1f + (float)((unsigned int)rec.y & 0xFFFFu) * EA_SCALE;
            float v = sqrtf(fabsf(dp2) / k + 1e-6f);
            float f = (dp2 > 0.f) ? v : ((dp2 < 0.f) ? -v : 0.f);
            out[NN + rec.w] = f;
            acc += f;
            atomicAdd(&g_balance[rec.x], -f);
        }
        #pragma unroll
        for (int off = 16; off > 0; off >>= 1) acc += __shfl_xor_sync(0xffffffffu, acc, off);
        if (lane == 0) g_insum[n] = acc;
    }
}

__global__ void reduce_kernel(const float* __restrict__ x, float* __restrict__ out) {
    __shared__ float sred[8];
    float loc = 0.f;
    for (int n = blockIdx.x * blockDim.x + threadIdx.x; n < NN; n += gridDim.x * blockDim.x) {
        float v = g_insum[n] + g_balance[n] + x[n * 4];
        loc += v * v;
    }
    #pragma unroll
    for (int off = 16; off > 0; off >>= 1) loc += __shfl_xor_sync(0xffffffffu, loc, off);
    int wid = threadIdx.x >> 5;
    if ((threadIdx.x & 31) == 0) sred[wid] = loc;
    __syncthreads();
    if (threadIdx.x == 0) {
        float tot = 0.f;
        for (int w = 0; w < (int)(blockDim.x >> 5); w++) tot += sred[w];
        atomicAdd(&g_imb, tot);
        __threadfence();
        int d = atomicAdd(&g_done, 1);
        if (d == (int)gridDim.x - 1) out[NN + EE] = sqrtf(g_imb);
    }
}

// ---------------- launch ----------------
extern "C" void kernel_launch(void* const* d_in, const int* in_sizes, int n_in,
                              void* d_out, int out_size) {
    const float*  x    = (const float*)d_in[0];
    const float4* x4   = (const float4*)d_in[0];
    const float4* ea4  = (const float4*)d_in[1];
    const void*   ei   = d_in[2];
    const float*  W1   = (const float*)d_in[3];
    const float*  b1   = (const float*)d_in[4];
    const float*  W2   = (const float*)d_in[5];
    const float*  b2   = (const float*)d_in[6];
    const float*  Wf   = (const float*)d_in[7];
    const float*  bf   = (const float*)d_in[8];
    float* out = (float*)d_out;

    const int TB = 256;
    const int gN  = (NN + TB - 1) / TB;
    const int gN4 = (NN * 4 + TB - 1) / TB;
    const int gE  = (EE + TB - 1) / TB;
    const int nScanBlocks = (NN + 1023) / 1024;

    count_kernel<<<gE, TB>>>(ei);
    scan1_kernel<<<nScanBlocks, 1024>>>();
    scan23_kernel<<<gN, TB>>>(nScanBlocks);
    scatter_kernel<<<gE, TB>>>(ei, ea4);

    for (int l = 0; l < LL; l++) {
        node_kernel<<<gN4, TB>>>(x4, W1, b1, W2, b2, l);
        edge_kernel<<<6250, 128>>>(W1, l);
    }

    final_kernel<<<gN, TB>>>(x, W2, b2, Wf, bf, out);
    flows_kernel<<<4096, 128>>>(out);
    reduce_kernel<<<512, TB>>>(x, out);
}

// round 16
// speedup vs baseline: 1.0357x; 1.0025x over previous
#include <cuda_runtime.h>
#include <cuda_fp16.h>
#include <cstdint>
#include <math.h>

#define NN 100000
#define EE 3200000
#define LL 8

#define EA_SCALE  (0.9f / 65535.0f)
#define EA_ISCALE (65535.0f / 0.9f)
#define EA_FOLD   (0.1f - 8388608.0f * EA_SCALE)

// ---------------- scratch ----------------
__device__ int4   g_rec_s[EE];        // {src, ea_lo, ea_hi, eid} dst-sorted
__device__ int    g_cnt[NN];
__device__ int    g_rowptr[NN + 1];
__device__ int    g_cursor[NN];
__device__ uint2  g_presrc_h[NN * 4]; // per-node 16 fp16 (4 halves per q-lane)
__device__ float4 g_predst[NN * 4];
__device__ float4 g_S[NN * 4];
__device__ float  g_P[NN];
__device__ float  g_balance[NN];
__device__ float  g_insum[NN];
__device__ int    g_blocksums[128];
__device__ float  g_imb;
__device__ int    g_done;

// ---------------- f32x2 helpers ----------------
__device__ __forceinline__ unsigned long long pk2(float lo, float hi) {
    unsigned long long r;
    asm("mov.b64 %0, {%1,%2};" : "=l"(r) : "f"(lo), "f"(hi));
    return r;
}
__device__ __forceinline__ void upk2(unsigned long long v, float& lo, float& hi) {
    asm("mov.b64 {%0,%1}, %2;" : "=f"(lo), "=f"(hi) : "l"(v));
}
__device__ __forceinline__ unsigned long long fma2(unsigned long long a, unsigned long long b, unsigned long long c) {
    unsigned long long d;
    asm("fma.rn.f32x2 %0, %1, %2, %3;" : "=l"(d) : "l"(a), "l"(b), "l"(c));
    return d;
}
__device__ __forceinline__ unsigned long long add2(unsigned long long a, unsigned long long b) {
    unsigned long long d;
    asm("add.rn.f32x2 %0, %1, %2;" : "=l"(d) : "l"(a), "l"(b));
    return d;
}
__device__ __forceinline__ float mag_lo(unsigned int w) {
    unsigned int r;
    asm("prmt.b32 %0, %1, %2, %3;" : "=r"(r) : "r"(w), "r"(0x00004B00u), "r"(0x5410u));
    return __uint_as_float(r);
}
__device__ __forceinline__ float mag_hi(unsigned int w) {
    unsigned int r;
    asm("prmt.b32 %0, %1, %2, %3;" : "=r"(r) : "r"(w), "r"(0x00004B00u), "r"(0x5432u));
    return __uint_as_float(r);
}
__device__ __forceinline__ unsigned long long h2_to_f32x2(unsigned int h2bits) {
    __half2 h = *(__half2*)&h2bits;
    float2 f = __half22float2(h);
    return pk2(f.x, f.y);
}

// ---------------- prep ----------------
__device__ __forceinline__ unsigned int quant_ea(float v) {
    float q = (v - 0.1f) * EA_ISCALE;
    q = fminf(fmaxf(q, 0.f), 65535.f);
    return __float2uint_rn(q);
}

__device__ __forceinline__ bool detect64(const long long* p64) {
    bool is64 = true;
    #pragma unroll
    for (int j = 0; j < 8; j++) {
        long long v = p64[j];
        if (v < 0 || v >= NN) is64 = false;
    }
    return is64;
}

__global__ void count_kernel(const void* ei) {
    int e = blockIdx.x * blockDim.x + threadIdx.x;
    if (e >= EE) return;
    const long long* p64 = (const long long*)ei;
    int d;
    if (detect64(p64)) d = (int)p64[e + EE];
    else               d = ((const int*)ei)[e + EE];
    atomicAdd(&g_cnt[d], 1);
}

__global__ void scan1_kernel() {
    __shared__ int s[1024];
    int tx = threadIdx.x;
    int i = blockIdx.x * 1024 + tx;
    s[tx] = (i < NN) ? g_cnt[i] : 0;
    __syncthreads();
    for (int off = 1; off < 1024; off <<= 1) {
        int t = (tx >= off) ? s[tx - off] : 0;
        __syncthreads();
        s[tx] += t;
        __syncthreads();
    }
    if (i < NN) g_rowptr[i + 1] = s[tx];
    if (tx == 1023) g_blocksums[blockIdx.x] = s[1023];
}

__global__ void scan23_kernel(int nblocks) {
    __shared__ int sb[128];
    int t = threadIdx.x;
    if (t < 128) sb[t] = (t < nblocks) ? g_blocksums[t] : 0;
    __syncthreads();
    if (t == 0) {
        int run = 0;
        for (int b = 0; b < nblocks; b++) { int c = sb[b]; sb[b] = run; run += c; }
    }
    __syncthreads();
    int i = blockIdx.x * blockDim.x + t;
    if (i >= NN) return;
    int off = sb[i >> 10];
    int rp = g_rowptr[i + 1] + off;
    g_rowptr[i + 1] = rp;
    g_cursor[i] = rp - g_cnt[i];
    g_cnt[i] = 0;
    g_balance[i] = 0.f;
    if (i == 0) { g_rowptr[0] = 0; g_imb = 0.f; g_done = 0; }
}

__global__ void scatter_kernel(const void* ei, const float4* __restrict__ ea4) {
    int e = blockIdx.x * blockDim.x + threadIdx.x;
    if (e >= EE) return;
    const long long* p64 = (const long long*)ei;
    int s, d;
    if (detect64(p64)) {
        s = (int)p64[e]; d = (int)p64[e + EE];
    } else {
        const int* p32 = (const int*)ei;
        s = p32[e]; d = p32[e + EE];
    }
    float4 ea = ea4[e];
    int p = atomicAdd(&g_cursor[d], 1);
    int4 rec;
    rec.x = s;
    rec.y = (int)(quant_ea(ea.x) | (quant_ea(ea.y) << 16));
    rec.z = (int)(quant_ea(ea.z) | (quant_ea(ea.w) << 16));
    rec.w = e;
    g_rec_s[p] = rec;
}

// ---------------- per-layer node kernel (shuffle-reduced X computation) ----------------
__global__ void node_kernel(const float4* __restrict__ x4,
                            const float* __restrict__ W1, const float* __restrict__ b1,
                            const float* __restrict__ W2, const float* __restrict__ b2,
                            int l) {
    __shared__ float sW1[384], sb1[16], sW2[96], sb2[6];
    int t = threadIdx.x;
    for (int i = t; i < 384; i += blockDim.x) sW1[i] = W1[l * 384 + i];
    if (t < 16) sb1[t] = b1[l * 16 + t];
    if (l > 0) {
        for (int i = t; i < 96; i += blockDim.x) sW2[i] = W2[(l - 1) * 96 + i];
        if (t < 6) sb2[t] = b2[(l - 1) * 6 + t];
    }
    __syncthreads();
    int tid = blockIdx.x * blockDim.x + t;
    if (tid >= NN * 4) return;
    int n = tid >> 2, q = tid & 3;

    float X[6];
    if (l == 0) {
        #pragma unroll
        for (int k = 0; k < 6; k++) X[k] = 0.f;
    } else {
        int cnt = g_rowptr[n + 1] - g_rowptr[n];
        float inv = 1.0f / (float)max(cnt, 1);
        float fc = (float)cnt;
        float4 sq = g_S[n * 4 + q];        // this lane's quarter only
        float pk_[6];
        #pragma unroll
        for (int k = 0; k < 6; k++) {
            float a = sq.x * sW2[(q * 4 + 0) * 6 + k];
            a = fmaf(sq.y, sW2[(q * 4 + 1) * 6 + k], a);
            a = fmaf(sq.z, sW2[(q * 4 + 2) * 6 + k], a);
            a = fmaf(sq.w, sW2[(q * 4 + 3) * 6 + k], a);
            pk_[k] = a;
        }
        #pragma unroll
        for (int off = 1; off <= 2; off <<= 1) {
            #pragma unroll
            for (int k = 0; k < 6; k++)
                pk_[k] += __shfl_xor_sync(0xffffffffu, pk_[k], off);
        }
        #pragma unroll
        for (int k = 0; k < 6; k++)
            X[k] = fmaxf(fmaf(fc, sb2[k], pk_[k]) * inv, 0.f);
    }
    float4 na = x4[n];
    float ps[4], pd[4];
    #pragma unroll
    for (int jj = 0; jj < 4; jj++) {
        int j = q * 4 + jj;
        float a = 0.f, b = sb1[j];
        #pragma unroll
        for (int i = 0; i < 6; i++) {
            a = fmaf(X[i], sW1[i * 16 + j], a);
            b = fmaf(X[i], sW1[(6 + i) * 16 + j], b);
        }
        a = fmaf(na.x, sW1[12 * 16 + j], a);
        a = fmaf(na.y, sW1[13 * 16 + j], a);
        a = fmaf(na.z, sW1[14 * 16 + j], a);
        a = fmaf(na.w, sW1[15 * 16 + j], a);
        b = fmaf(na.x, sW1[16 * 16 + j], b);
        b = fmaf(na.y, sW1[17 * 16 + j], b);
        b = fmaf(na.z, sW1[18 * 16 + j], b);
        b = fmaf(na.w, sW1[19 * 16 + j], b);
        ps[jj] = a; pd[jj] = b;
    }
    __half2 h01 = __floats2half2_rn(ps[0], ps[1]);
    __half2 h23 = __floats2half2_rn(ps[2], ps[3]);
    uint2 u;
    u.x = *(unsigned int*)&h01;
    u.y = *(unsigned int*)&h23;
    g_presrc_h[n * 4 + q] = u;
    g_predst[n * 4 + q] = make_float4(pd[0], pd[1], pd[2], pd[3]);
}

// ---------------- per-layer edge kernel: QUARTER-WARP per node, 3-stage pipeline ----------------
__global__ void __launch_bounds__(128) edge_kernel(const float* __restrict__ W1, int l) {
    int lane = threadIdx.x & 31;
    int grp = lane >> 3;
    int q = lane & 3;
    int eslot = (lane >> 2) & 1;
    const float* wp = W1 + l * 384 + 20 * 16 + q * 4;
    float4 w0 = *(const float4*)(wp);
    float4 w1 = *(const float4*)(wp + 16);
    float4 w2 = *(const float4*)(wp + 32);
    float4 w3 = *(const float4*)(wp + 48);
    float4 base;
    base.x = EA_FOLD * (w0.x + w1.x + w2.x + w3.x);
    base.y = EA_FOLD * (w0.y + w1.y + w2.y + w3.y);
    base.z = EA_FOLD * (w0.z + w1.z + w2.z + w3.z);
    base.w = EA_FOLD * (w0.w + w1.w + w2.w + w3.w);
    unsigned long long W0a = pk2(w0.x * EA_SCALE, w0.y * EA_SCALE);
    unsigned long long W0b = pk2(w0.z * EA_SCALE, w0.w * EA_SCALE);
    unsigned long long W1a = pk2(w1.x * EA_SCALE, w1.y * EA_SCALE);
    unsigned long long W1b = pk2(w1.z * EA_SCALE, w1.w * EA_SCALE);
    unsigned long long W2a = pk2(w2.x * EA_SCALE, w2.y * EA_SCALE);
    unsigned long long W2b = pk2(w2.z * EA_SCALE, w2.w * EA_SCALE);
    unsigned long long W3a = pk2(w3.x * EA_SCALE, w3.y * EA_SCALE);
    unsigned long long W3b = pk2(w3.z * EA_SCALE, w3.w * EA_SCALE);

    int warp = (blockIdx.x * blockDim.x + threadIdx.x) >> 5;
    int nwarps = (gridDim.x * blockDim.x) >> 5;
    const int NQUAD = NN / 4;
    for (int idx = warp; idx < NQUAD; idx += nwarps) {
        int n = idx * 4 + grp;
        int rs = g_rowptr[n], re = g_rowptr[n + 1];
        float4 pd = g_predst[n * 4 + q];
        unsigned long long pdA = pk2(pd.x + base.x, pd.y + base.y);
        unsigned long long pdB = pk2(pd.z + base.z, pd.w + base.w);
        float ax = 0.f, ay = 0.f, az = 0.f, aw = 0.f;
        if (re > rs) {
            int last = re - 1;
            int p0base = rs + eslot;
            int4 cA0 = g_rec_s[min(p0base,     last)];
            int4 cB0 = g_rec_s[min(p0base + 2, last)];
            int4 cA1 = g_rec_s[min(p0base + 4, last)];
            int4 cB1 = g_rec_s[min(p0base + 6, last)];
            uint2 hA0 = g_presrc_h[cA0.x * 4 + q];
            uint2 hB0 = g_presrc_h[cB0.x * 4 + q];
            for (int p0 = rs; p0 < re; p0 += 4) {
                int nA = p0 + 8 + eslot;
                int4 cA2 = g_rec_s[min(nA,     last)];
                int4 cB2 = g_rec_s[min(nA + 2, last)];
                uint2 hA1 = g_presrc_h[cA1.x * 4 + q];
                uint2 hB1 = g_presrc_h[cB1.x * 4 + q];
                bool vA = (p0 + eslot) < re;
                bool vB = (p0 + 2 + eslot) < re;
                {
                    unsigned long long ps01 = h2_to_f32x2(hA0.x);
                    unsigned long long ps23 = h2_to_f32x2(hA0.y);
                    unsigned int ex = (unsigned int)cA0.y, ey = (unsigned int)cA0.z;
                    float f0 = mag_lo(ex), f1 = mag_hi(ex);
                    float f2 = mag_lo(ey), f3 = mag_hi(ey);
                    unsigned long long A0 = pk2(f0, f0), A1 = pk2(f1, f1);
                    unsigned long long A2 = pk2(f2, f2), A3 = pk2(f3, f3);
                    unsigned long long h01 = add2(ps01, pdA);
                    unsigned long long h23 = add2(ps23, pdB);
                    h01 = fma2(A0, W0a, h01); h23 = fma2(A0, W0b, h23);
                    h01 = fma2(A1, W1a, h01); h23 = fma2(A1, W1b, h23);
                    h01 = fma2(A2, W2a, h01); h23 = fma2(A2, W2b, h23);
                    h01 = fma2(A3, W3a, h01); h23 = fma2(A3, W3b, h23);
                    float hx, hy, hz, hw;
                    upk2(h01, hx, hy); upk2(h23, hz, hw);
                    if (vA) {
                        ax += fmaxf(hx, 0.f); ay += fmaxf(hy, 0.f);
                        az += fmaxf(hz, 0.f); aw += fmaxf(hw, 0.f);
                    }
                }
                {
                    unsigned long long ps01 = h2_to_f32x2(hB0.x);
                    unsigned long long ps23 = h2_to_f32x2(hB0.y);
                    unsigned int ex = (unsigned int)cB0.y, ey = (unsigned int)cB0.z;
                    float f0 = mag_lo(ex), f1 = mag_hi(ex);
                    float f2 = mag_lo(ey), f3 = mag_hi(ey);
                    unsigned long long A0 = pk2(f0, f0), A1 = pk2(f1, f1);
                    unsigned long long A2 = pk2(f2, f2), A3 = pk2(f3, f3);
                    unsigned long long h01 = add2(ps01, pdA);
                    unsigned long long h23 = add2(ps23, pdB);
                    h01 = fma2(A0, W0a, h01); h23 = fma2(A0, W0b, h23);
                    h01 = fma2(A1, W1a, h01); h23 = fma2(A1, W1b, h23);
                    h01 = fma2(A2, W2a, h01); h23 = fma2(A2, W2b, h23);
                    h01 = fma2(A3, W3a, h01); h23 = fma2(A3, W3b, h23);
                    float hx, hy, hz, hw;
                    upk2(h01, hx, hy); upk2(h23, hz, hw);
                    if (vB) {
                        ax += fmaxf(hx, 0.f); ay += fmaxf(hy, 0.f);
                        az += fmaxf(hz, 0.f); aw += fmaxf(hw, 0.f);
                    }
                }
                cA0 = cA1; cB0 = cB1;
                cA1 = cA2; cB1 = cB2;
                hA0 = hA1; hB0 = hB1;
            }
        }
        ax += __shfl_xor_sync(0xffffffffu, ax, 4);
        ay += __shfl_xor_sync(0xffffffffu, ay, 4);
        az += __shfl_xor_sync(0xffffffffu, az, 4);
        aw += __shfl_xor_sync(0xffffffffu, aw, 4);
        if (eslot == 0) g_S[n * 4 + q] = make_float4(ax, ay, az, aw);
    }
}

// ---------------- epilogue ----------------
__global__ void final_kernel(const float* __restrict__ x,
                             const float* __restrict__ W2, const float* __restrict__ b2,
                             const float* __restrict__ Wf, const float* __restrict__ bf,
                             float* __restrict__ out) {
    __shared__ float sW2[96], sb2[6], sWf[6], sbf;
    int t = threadIdx.x;
    for (int i = t; i < 96; i += blockDim.x) sW2[i] = W2[7 * 96 + i];
    if (t < 6) { sb2[t] = b2[7 * 6 + t]; sWf[t] = Wf[t]; }
    if (t == 0) sbf = bf[0];
    __syncthreads();
    int n = blockIdx.x * blockDim.x + t;
    if (n >= NN) return;
    int cnt = g_rowptr[n + 1] - g_rowptr[n];
    float inv = 1.0f / (float)max(cnt, 1);
    float fc = (float)cnt;
    float4 s0 = g_S[n * 4 + 0], s1 = g_S[n * 4 + 1], s2 = g_S[n * 4 + 2], s3 = g_S[n * 4 + 3];
    float Sv[16] = { s0.x, s0.y, s0.z, s0.w, s1.x, s1.y, s1.z, s1.w,
                     s2.x, s2.y, s2.z, s2.w, s3.x, s3.y, s3.z, s3.w };
    float P = sbf;
    #pragma unroll
    for (int k = 0; k < 6; k++) {
        float a = fc * sb2[k];
        #pragma unroll
        for (int j = 0; j < 16; j++) a = fmaf(Sv[j], sW2[j * 6 + k], a);
        float Xk = fmaxf(a * inv, 0.f);
        P = fmaf(Xk, sWf[k], P);
    }
    P = fmaxf(P, 0.f);
    out[n] = P;
    float fixedv = x[n * 4 + 3];
    g_P[n] = (fixedv != 0.f) ? fixedv : P;
}

// flows: QUARTER-WARP per node (same layout as edge kernel) — 4 node chains/warp.
__global__ void __launch_bounds__(128) flows_kernel(float* __restrict__ out) {
    int lane = threadIdx.x & 31;
    int grp = lane >> 3;
    int sub = lane & 7;
    int warp = (blockIdx.x * blockDim.x + threadIdx.x) >> 5;
    int nwarps = (gridDim.x * blockDim.x) >> 5;
    const int NQUAD = NN / 4;
    for (int idx = warp; idx < NQUAD; idx += nwarps) {
        int n = idx * 4 + grp;
        int rs = g_rowptr[n], re = g_rowptr[n + 1];
        float Pd = g_P[n];
        float Pd2 = Pd * Pd;
        float acc = 0.f;
        for (int p = rs + sub; p < re; p += 8) {
            int4 rec = g_rec_s[p];
            float Ps = g_P[rec.x];
            float dp2 = Ps * Ps - Pd2;
            float k = 0.1f + (float)((unsigned int)rec.y & 0xFFFFu) * EA_SCALE;
            float v = sqrtf(fabsf(dp2) / k + 1e-6f);
            float f = (dp2 > 0.f) ? v : ((dp2 < 0.f) ? -v : 0.f);
            out[NN + rec.w] = f;
            acc += f;
            atomicAdd(&g_balance[rec.x], -f);
        }
        // reduce across the 8-lane group (offsets 1,2,4 stay inside the aligned group)
        #pragma unroll
        for (int off = 1; off <= 4; off <<= 1) acc += __shfl_xor_sync(0xffffffffu, acc, off);
        if (sub == 0) g_insum[n] = acc;
    }
}

__global__ void reduce_kernel(const float* __restrict__ x, float* __restrict__ out) {
    __shared__ float sred[8];
    float loc = 0.f;
    for (int n = blockIdx.x * blockDim.x + threadIdx.x; n < NN; n += gridDim.x * blockDim.x) {
        float v = g_insum[n] + g_balance[n] + x[n * 4];
        loc += v * v;
    }
    #pragma unroll
    for (int off = 16; off > 0; off >>= 1) loc += __shfl_xor_sync(0xffffffffu, loc, off);
    int wid = threadIdx.x >> 5;
    if ((threadIdx.x & 31) == 0) sred[wid] = loc;
    __syncthreads();
    if (threadIdx.x == 0) {
        float tot = 0.f;
        for (int w = 0; w < (int)(blockDim.x >> 5); w++) tot += sred[w];
        atomicAdd(&g_imb, tot);
        __threadfence();
        int d = atomicAdd(&g_done, 1);
        if (d == (int)gridDim.x - 1) out[NN + EE] = sqrtf(g_imb);
    }
}

// ---------------- launch ----------------
extern "C" void kernel_launch(void* const* d_in, const int* in_sizes, int n_in,
                              void* d_out, int out_size) {
    const float*  x    = (const float*)d_in[0];
    const float4* x4   = (const float4*)d_in[0];
    const float4* ea4  = (const float4*)d_in[1];
    const void*   ei   = d_in[2];
    const float*  W1   = (const float*)d_in[3];
    const float*  b1   = (const float*)d_in[4];
    const float*  W2   = (const float*)d_in[5];
    const float*  b2   = (const float*)d_in[6];
    const float*  Wf   = (const float*)d_in[7];
    const float*  bf   = (const float*)d_in[8];
    float* out = (float*)d_out;

    const int TB = 256;
    const int gN  = (NN + TB - 1) / TB;
    const int gN4 = (NN * 4 + TB - 1) / TB;
    const int gE  = (EE + TB - 1) / TB;
    const int nScanBlocks = (NN + 1023) / 1024;

    count_kernel<<<gE, TB>>>(ei);
    scan1_kernel<<<nScanBlocks, 1024>>>();
    scan23_kernel<<<gN, TB>>>(nScanBlocks);
    scatter_kernel<<<gE, TB>>>(ei, ea4);

    for (int l = 0; l < LL; l++) {
        node_kernel<<<gN4, TB>>>(x4, W1, b1, W2, b2, l);
        edge_kernel<<<6250, 128>>>(W1, l);
    }

    final_kernel<<<gN, TB>>>(x, W2, b2, Wf, bf, out);
    flows_kernel<<<6250, 128>>>(out);
    reduce_kernel<<<512, TB>>>(x, out);
}